// round 14
// baseline (speedup 1.0000x reference)
#include <cuda_runtime.h>
#include <cstdint>

// ---------------- configuration ----------------
#define S           256         // tile table width (num_tile<=16 -> nt2<=256)
#define RP          1024        // rows pad; N up to 4.19M
#define PPB         4096        // points per block
#define WPB         16          // warps per block (512 threads)
#define PPW         256         // contiguous points per warp
#define ITERS       (PPW / 32)  // 8
#define HTHREADS    512

// ---------------- static scratch (no runtime allocation) ----------------
__device__ int      g_hist [S * RP];     // column-major [tile][row] counts -> excl prefixes
__device__ int      g_lbase[RP * S];     // per-block tile-local exclusive base
__device__ int      g_tot  [S];          // per-tile totals
__device__ int      g_offsets[S];        // global tile offsets
__device__ unsigned g_packed[RP * PPB];  // per-point (block-sorted local pos <<16 | key)

// ---------------- helpers ----------------
__device__ __forceinline__ int tile_of(float v, float ts, int nt) {
    int t = (int)floorf(v / ts);
    t = t < 0 ? 0 : t;
    t = t > nt - 1 ? nt - 1 : t;
    return t;
}

// ---- pass 1: block histogram + stable block-local sorted position ----
__global__ void k_hist(const float2* __restrict__ pos,
                       const int* __restrict__ p_nt, int N) {
    __shared__ int sh[WPB * S];   // 16 KB per-warp counters -> warp bases
    __shared__ int s2[S];         // tile totals -> inclusive scan
    __shared__ int sL[S];         // tile-local exclusive base
    const int nt  = *p_nt;
    const int nt2 = nt * nt;
    const float ts = 1024.0f / (float)nt;

    const int tid  = threadIdx.x;
    const int w    = tid >> 5;
    const int lane = tid & 31;
    const int row  = blockIdx.x;

    for (int t = tid; t < WPB * S; t += HTHREADS) sh[t] = 0;
    __syncthreads();

    const int base = row * PPB + w * PPW;   // warp owns contiguous span
    const unsigned lt_mask = (1u << lane) - 1u;

    // prefetch keys (independent of the rank chain)
    int keys[ITERS];
#pragma unroll
    for (int i = 0; i < ITERS; i++) {
        int idx = base + i * 32 + lane;
        if (idx < N) {
            float2 p = __ldg(&pos[idx]);
            keys[i] = tile_of(p.y, ts, nt) * nt + tile_of(p.x, ts, nt);
        } else {
            keys[i] = -1;
        }
    }

    // serial stable-rank chain on per-warp counters
    int ranks[ITERS];
#pragma unroll
    for (int i = 0; i < ITERS; i++) {
        int key = keys[i];
        bool valid = key >= 0;

        unsigned m  = __match_any_sync(0xFFFFFFFFu, key);
        int leader  = __ffs(m) - 1;
        int cnt     = __popc(m);
        int rank_lt = __popc(m & lt_mask);

        int old = 0;
        if (lane == leader && valid) {
            old = sh[w * S + key];            // single writer per address
            sh[w * S + key] = old + cnt;
        }
        old = __shfl_sync(0xFFFFFFFFu, old, leader);
        ranks[i] = old + rank_lt;
    }
    __syncthreads();

    // combine: warp-exclusive prefix per tile; block totals (column-major store)
    int tot = 0;
    if (tid < S) {
        int run = 0;
#pragma unroll
        for (int w2 = 0; w2 < WPB; w2++) {
            int v = sh[w2 * S + tid];
            sh[w2 * S + tid] = run;
            run += v;
        }
        tot = run;
        s2[tid] = run;
        if (tid < nt2) g_hist[(size_t)tid * RP + row] = run;
    }
    __syncthreads();

    // exclusive scan over tiles -> block-local sorted base per tile
    for (int off = 1; off < S; off <<= 1) {
        int v = (tid < S && tid >= off) ? s2[tid - off] : 0;
        __syncthreads();
        if (tid < S) s2[tid] += v;
        __syncthreads();
    }
    if (tid < S) {
        sL[tid] = s2[tid] - tot;
        if (tid < nt2) g_lbase[(size_t)row * S + tid] = sL[tid];
    }
    __syncthreads();

    // emit packed: key | block-sorted local position << 16  (local pos < 4096)
#pragma unroll
    for (int i = 0; i < ITERS; i++) {
        int key = keys[i];
        if (key >= 0) {
            int idx = base + i * 32 + lane;
            int ld  = sL[key] + sh[w * S + key] + ranks[i];
            g_packed[idx] = (unsigned)key | ((unsigned)ld << 16);
        }
    }
}

// ---- pass 2a: per-tile scan over rows (contiguous column, one block/tile) ----
__global__ void k_scan(const int* __restrict__ p_nt, int ROWS) {
    __shared__ int s[1024];
    const int nt2 = (*p_nt) * (*p_nt);
    const int t = blockIdx.x;
    if (t >= nt2) return;

    const int r = threadIdx.x;
    int v = (r < ROWS) ? g_hist[(size_t)t * RP + r] : 0;
    s[r] = v;
    __syncthreads();

    for (int off = 1; off < 1024; off <<= 1) {
        int x = (r >= off) ? s[r - off] : 0;
        __syncthreads();
        s[r] += x;
        __syncthreads();
    }

    if (r < ROWS) g_hist[(size_t)t * RP + r] = s[r] - v;   // exclusive prefix
    if (r == 1023) g_tot[t] = s[1023];
}

// ---- pass 2b: scan tile totals -> global offsets; emit counts/offsets ----
__global__ void k_offsets(const int* __restrict__ p_nt, float* __restrict__ out, int N) {
    __shared__ int s[256];
    const int nt2 = (*p_nt) * (*p_nt);
    const int t = threadIdx.x;

    int v = (t < nt2) ? g_tot[t] : 0;
    s[t] = v;
    __syncthreads();

    for (int off = 1; off < 256; off <<= 1) {
        int x = (t >= off) ? s[t - off] : 0;
        __syncthreads();
        s[t] += x;
        __syncthreads();
    }
    int excl = s[t] - v;

    if (t < nt2) {
        g_offsets[t] = excl;
        size_t feat_sz = (size_t)7 * (size_t)N;
        out[feat_sz + t]       = (float)v;     // tile_counts
        out[feat_sz + nt2 + t] = (float)excl;  // tile_offsets
    }
}

// ---- pass 3: fused sort: coalesced in, SMEM-staged, run-coalesced out ----
// dynamic smem: feat staging (PPB*7 floats = 112KB) + stage (PPB u32 = 16KB) + D (1KB)
__global__ void k_sort(const float2* __restrict__ pos,
                       const float4* __restrict__ cov,
                       const float*  __restrict__ opac,
                       const int*    __restrict__ p_nt,
                       int N, float* __restrict__ out) {
    extern __shared__ float smem[];
    float*    featS = smem;                          // PPB*7 floats
    unsigned* stage = (unsigned*)(smem + PPB * 7);   // PPB u32
    int*      D     = (int*)(stage + PPB);           // S ints

    const int nt2 = (*p_nt) * (*p_nt);
    const int tid = threadIdx.x;
    const int row = blockIdx.x;
    const int base = row * PPB;
    const int nv = min(PPB, N - base);

    float* __restrict__ out_order = out + (size_t)7 * (size_t)N + 2 * (size_t)nt2;

    if (tid < nt2)
        D[tid] = g_offsets[tid]
               + g_hist[(size_t)tid * RP + row]
               - g_lbase[(size_t)row * S + tid];
    __syncthreads();

    // phase 1: coalesced load + feat compute, scatter into SMEM at sorted slot
#pragma unroll
    for (int i = 0; i < PPB / HTHREADS; i++) {
        int j = tid + i * HTHREADS;
        if (j < nv) {
            int idx = base + j;
            unsigned pk = g_packed[idx];      // coalesced
            int ld = (int)(pk >> 16);

            float2 p  = __ldg(&pos[idx]);
            float4 cv = __ldg(&cov[idx]);
            float  op = __ldg(&opac[idx]);

            float a = cv.x, b = cv.y, c = cv.z, d = cv.w;
            float tr  = a + d;
            float det = a * d - b * c;
            float t1  = 0.5f * tr;
            float t2  = 0.5f * sqrtf(fmaxf(tr * tr - 4.0f * det, 0.0f));
            float rad = fmaxf(t1 - t2, t1 + t2);
            float inv_det = 1.0f / det;

            float* sf = featS + ld * 7;       // stride 7 -> conflict-free
            sf[0] = p.x;  sf[1] = p.y;
            sf[2] =  d * inv_det;
            sf[3] = -b * inv_det;
            sf[4] =  a * inv_det;
            sf[5] = op;   sf[6] = rad;

            stage[ld] = ((pk & 0xFFFFu) << 16) | (unsigned)j;
        }
    }
    __syncthreads();

    // phase 2: sorted-slot order writeout -> run-coalesced global stores
#pragma unroll
    for (int i = 0; i < PPB / HTHREADS; i++) {
        int j = tid + i * HTHREADS;
        if (j < nv) {
            unsigned v = stage[j];
            int dst = j + D[v >> 16];
            const float* sf = featS + j * 7;
            float* f = out + (size_t)dst * 7;
#pragma unroll
            for (int c = 0; c < 7; c++) f[c] = sf[c];
            out_order[dst] = (float)(base + (int)(v & 0xFFFFu));
        }
    }
}

// ---------------- launch ----------------
extern "C" void kernel_launch(void* const* d_in, const int* in_sizes, int n_in,
                              void* d_out, int out_size) {
    const float2* pos  = (const float2*)d_in[0];
    const float4* cov  = (const float4*)d_in[1];
    const float*  opac = (const float*) d_in[2];
    const int*    p_nt = (const int*)   d_in[3];
    float* out = (float*)d_out;

    const int N    = in_sizes[0] / 2;
    const int ROWS = (N + PPB - 1) / PPB;

    const int SORT_SMEM = PPB * 7 * 4 + PPB * 4 + S * 4;  // 112KB + 16KB + 1KB
    static bool attr_set = false;
    if (!attr_set) {
        cudaFuncSetAttribute(k_sort, cudaFuncAttributeMaxDynamicSharedMemorySize, SORT_SMEM);
        attr_set = true;
    }

    k_hist   <<<ROWS, HTHREADS>>>(pos, p_nt, N);
    k_scan   <<<S, 1024>>>(p_nt, ROWS);
    k_offsets<<<1, 256>>>(p_nt, out, N);
    k_sort   <<<ROWS, HTHREADS, SORT_SMEM>>>(pos, cov, opac, p_nt, N, out);
}